// round 15
// baseline (speedup 1.0000x reference)
#include <cuda_runtime.h>
#include <cuda_fp16.h>
#include <mma.h>
#include <cstdint>

using namespace nvcuda;

#define N_NODES 100000
#define N_EDGES 1600000
#define IN_F 128
#define HID 64
#define EMB 32
#define SCAN_CHUNK 1024
#define NPART ((N_NODES + SCAN_CHUNK - 1) / SCAN_CHUNK)   // 98

#define GEMM_BLOCKS ((N_NODES + 63) / 64)                 // 1563
#define EB4 ((N_EDGES / 4 + 255) / 256)                   // 1563 (4 edges/thread)

#define NSPLIT_TILES 782
#define NSPLIT_NODES (NSPLIT_TILES * 64)                  // 50048
#define G1A_BLOCKS (NSPLIT_NODES * 32 / 256)              // 6256
#define G1B_BLOCKS ((N_NODES - NSPLIT_NODES) * 32 / 256 + 1)
#define GEMM2B_BLOCKS (GEMM_BLOCKS - NSPLIT_TILES)        // 781
#define NPAD 64                                           // WMMA store overrun pad

// ---------------- scratch (device globals; referenced ONLY in device code) ----
__device__ __align__(16) __half g_xlh[(N_NODES + NPAD) * HID]; // x @ W1_l (fp16)
__device__ __align__(16) float  g_xr [(N_NODES + NPAD) * HID]; // x @ W1_r (fp32)
__device__ __align__(16) float  g_agg1[N_NODES * HID];
__device__ __align__(16) __half g_hlh[N_NODES * EMB];
__device__ __align__(16) float  g_hr [N_NODES * EMB];
__device__ int g_deg[N_NODES];
__device__ int g_off[N_NODES + 1];
__device__ int g_cur[N_NODES];
__device__ int g_adj[N_EDGES];
__device__ int g_part[NPART];
__device__ int g_flag;
__device__ int g_stride;                                  // 1 = int32, 2 = int64

// ---------------- device bodies ----------------

// Layer-2 dual GEMM tile with fused layer-1 finish (f32x2, unchanged).
__device__ __forceinline__ void gemm2_tile(int tile,
                                           const float* __restrict__ Wl,
                                           const float* __restrict__ Wr,
                                           const float* __restrict__ b1) {
    __shared__ __align__(16) float ws2[32][64];
    __shared__ __align__(16) float xs2[32][64];

    int tid = threadIdx.x;
    int n0 = tile * 64;
    int rows = N_NODES - n0; if (rows > 64) rows = 64;
    int ty = tid >> 4, tx = tid & 15;
    int m0 = ty * 4;

    unsigned long long acc[4][2];
#pragma unroll
    for (int i = 0; i < 4; ++i)
#pragma unroll
        for (int j = 0; j < 2; ++j) acc[i][j] = 0ull;

    for (int kc = 0; kc < HID; kc += 32) {
        for (int idx = tid; idx < 512; idx += 256) {
            int k = idx >> 4;
            int n = (idx & 15) * 4;
            const float* src = (n < 32) ? &Wl[(kc + k) * 32 + n]
                                        : &Wr[(kc + k) * 32 + (n - 32)];
            *reinterpret_cast<float4*>(&ws2[k][n]) =
                *reinterpret_cast<const float4*>(src);
        }
        for (int idx = tid; idx < 512; idx += 256) {
            int m = idx & 63;
            int kv = (idx >> 6) * 4;
            int gr = n0 + m; if (gr >= N_NODES) gr = N_NODES - 1;
            float inv = 1.0f / (float)max(g_deg[gr], 1);
            float4 a = *reinterpret_cast<const float4*>(&g_agg1[(size_t)gr * HID + kc + kv]);
            float4 r = *reinterpret_cast<const float4*>(&g_xr[(size_t)gr * HID + kc + kv]);
            float4 b = *reinterpret_cast<const float4*>(&b1[kc + kv]);
            xs2[kv + 0][m] = fmaxf(fmaf(a.x, inv, b.x) + r.x, 0.f);
            xs2[kv + 1][m] = fmaxf(fmaf(a.y, inv, b.y) + r.y, 0.f);
            xs2[kv + 2][m] = fmaxf(fmaf(a.z, inv, b.z) + r.z, 0.f);
            xs2[kv + 3][m] = fmaxf(fmaf(a.w, inv, b.w) + r.w, 0.f);
        }
        __syncthreads();

#pragma unroll
        for (int k = 0; k < 32; ++k) {
            unsigned long long xv[4];
#pragma unroll
            for (int i = 0; i < 4; ++i) {
                float xf = xs2[k][m0 + i];
                asm("mov.b64 %0, {%1, %1};" : "=l"(xv[i]) : "f"(xf));
            }
            unsigned long long wv[2];
#pragma unroll
            for (int j = 0; j < 2; ++j)
                wv[j] = *reinterpret_cast<const unsigned long long*>(&ws2[k][2 * tx + 32 * j]);
#pragma unroll
            for (int i = 0; i < 4; ++i)
#pragma unroll
                for (int j = 0; j < 2; ++j)
                    asm("fma.rn.f32x2 %0, %1, %2, %0;"
                        : "+l"(acc[i][j]) : "l"(xv[i]), "l"(wv[j]));
        }
        __syncthreads();
    }

#pragma unroll
    for (int j = 0; j < 2; ++j) {
        int n = 2 * tx + 32 * j;
#pragma unroll
        for (int i = 0; i < 4; ++i) {
            if (m0 + i < rows) {
                float lo, hi;
                asm("mov.b64 {%0, %1}, %2;" : "=f"(lo), "=f"(hi) : "l"(acc[i][j]));
                size_t row = (size_t)(n0 + m0 + i);
                if (n < 32) {
                    *reinterpret_cast<__half2*>(&g_hlh[row * EMB + n]) =
                        __floats2half2_rn(lo, hi);
                } else {
                    *reinterpret_cast<float2*>(&g_hr[row * EMB + (n - 32)]) =
                        make_float2(lo, hi);
                }
            }
        }
    }
}

// Gather body for one (node, lane) pair.
__device__ __forceinline__ void gather1_body(int n, int lane) {
    const __half2* __restrict__ xl2 = reinterpret_cast<const __half2*>(g_xlh);
    int i = g_off[n], end = g_off[n + 1];
    float sx = 0.f, sy = 0.f;
    for (; i + 1 < end; i += 2) {
        int s0 = g_adj[i], s1 = g_adj[i + 1];
        float2 a = __half22float2(xl2[(size_t)s0 * 32 + lane]);
        float2 b = __half22float2(xl2[(size_t)s1 * 32 + lane]);
        sx += a.x + b.x; sy += a.y + b.y;
    }
    if (i < end) {
        float2 a = __half22float2(xl2[(size_t)g_adj[i] * 32 + lane]);
        sx += a.x; sy += a.y;
    }
    *reinterpret_cast<float2*>(&g_agg1[(size_t)n * HID + 2 * lane]) =
        make_float2(sx, sy);
}

// ---------------- kernels ----------------

// init: zero g_deg + scan flag; block 0 detects index dtype.
__global__ void k_init(const int* __restrict__ w) {
    int i = blockIdx.x * blockDim.x + threadIdx.x;
    if (i < N_NODES) g_deg[i] = 0;
    if (i == 0) g_flag = 0;
    if (blockIdx.x == 0) {
        __shared__ int nz;
        if (threadIdx.x == 0) nz = 0;
        __syncthreads();
        int cnt = 0;
        for (int k = threadIdx.x; k < 4096; k += blockDim.x)
            if (w[2 * k + 1] != 0) cnt++;
        atomicAdd(&nz, cnt);
        __syncthreads();
        if (threadIdx.x == 0) g_stride = (nz == 0) ? 2 : 1;
    }
}

// Layer-1 dual GEMM on TENSOR CORES (fp16 in, fp32 acc) — standalone.
// 8 warps: warp w -> row tile r = w>>1, col group g = w&1.
__global__ __launch_bounds__(256) void k_gemm1(const float* __restrict__ X,
                                               const float* __restrict__ Wl,
                                               const float* __restrict__ Wr) {
    __shared__ __align__(16) __half wsh[32][128];
    __shared__ __align__(16) __half xsh[64][40];
    __shared__ __align__(16) float  stage[4][16][20];

    int tid = threadIdx.x;
    int n0 = blockIdx.x * 64;
    int w = tid >> 5, lane = tid & 31;
    int r = w >> 1, g = w & 1;

    wmma::fragment<wmma::accumulator, 16, 16, 16, float> acc[4];
#pragma unroll
    for (int c = 0; c < 4; ++c) wmma::fill_fragment(acc[c], 0.0f);

    for (int kc = 0; kc < IN_F; kc += 32) {
        for (int idx = tid; idx < 1024; idx += 256) {
            int k = idx >> 5;
            int n4 = (idx & 31) * 4;
            const float* src = (n4 < 64) ? &Wl[(kc + k) * 64 + n4]
                                         : &Wr[(kc + k) * 64 + (n4 - 64)];
            float4 v = *reinterpret_cast<const float4*>(src);
            *reinterpret_cast<__half2*>(&wsh[k][n4])     = __floats2half2_rn(v.x, v.y);
            *reinterpret_cast<__half2*>(&wsh[k][n4 + 2]) = __floats2half2_rn(v.z, v.w);
        }
        for (int idx = tid; idx < 512; idx += 256) {
            int m = idx & 63;
            int kv = (idx >> 6) * 4;
            int gr = n0 + m; if (gr >= N_NODES) gr = N_NODES - 1;
            float4 v = *reinterpret_cast<const float4*>(&X[(size_t)gr * IN_F + kc + kv]);
            *reinterpret_cast<__half2*>(&xsh[m][kv])     = __floats2half2_rn(v.x, v.y);
            *reinterpret_cast<__half2*>(&xsh[m][kv + 2]) = __floats2half2_rn(v.z, v.w);
        }
        __syncthreads();

#pragma unroll
        for (int ks = 0; ks < 32; ks += 16) {
            wmma::fragment<wmma::matrix_a, 16, 16, 16, __half, wmma::row_major> af;
            wmma::load_matrix_sync(af, &xsh[r * 16][ks], 40);
#pragma unroll
            for (int c = 0; c < 4; ++c) {
                wmma::fragment<wmma::matrix_b, 16, 16, 16, __half, wmma::row_major> bf;
                wmma::load_matrix_sync(bf, &wsh[ks][g * 64 + c * 16], 128);
                wmma::mma_sync(acc[c], af, bf, acc[c]);
            }
        }
        __syncthreads();
    }

    if (g == 1) {
#pragma unroll
        for (int c = 0; c < 4; ++c)
            wmma::store_matrix_sync(&g_xr[(size_t)(n0 + r * 16) * HID + c * 16],
                                    acc[c], HID, wmma::mem_row_major);
    } else {
#pragma unroll
        for (int c = 0; c < 4; ++c) {
            wmma::store_matrix_sync(&stage[r][0][0], acc[c], 20, wmma::mem_row_major);
            __syncwarp();
            int row_i = lane >> 1, c0 = (lane & 1) * 8;
            const float* srow = &stage[r][row_i][c0];
            __align__(16) __half2 h[4];
#pragma unroll
            for (int q = 0; q < 4; ++q)
                h[q] = __floats2half2_rn(srow[2 * q], srow[2 * q + 1]);
            size_t grow = (size_t)(n0 + r * 16 + row_i);
            *reinterpret_cast<uint4*>(&g_xlh[grow * HID + c * 16 + c0]) =
                *reinterpret_cast<const uint4*>(h);
            __syncwarp();
        }
    }
}

// Degree histogram: 4 edges/thread (vector loads for MLP).
__global__ void k_degree(const int* __restrict__ ei) {
    int t = blockIdx.x * blockDim.x + threadIdx.x;
    int e0 = t * 4;
    if (e0 >= N_EDGES) return;
    int d[4];
    if (g_stride == 2) {
        const long long* p = (const long long*)ei;
        longlong2 a = *reinterpret_cast<const longlong2*>(&p[N_EDGES + e0]);
        longlong2 b = *reinterpret_cast<const longlong2*>(&p[N_EDGES + e0 + 2]);
        d[0] = (int)a.x; d[1] = (int)a.y; d[2] = (int)b.x; d[3] = (int)b.y;
    } else {
        int4 a = *reinterpret_cast<const int4*>(&ei[N_EDGES + e0]);
        d[0] = a.x; d[1] = a.y; d[2] = a.z; d[3] = a.w;
    }
#pragma unroll
    for (int i = 0; i < 4; ++i)
        if ((unsigned)d[i] < N_NODES) atomicAdd(&g_deg[d[i]], 1);
}

// Single-pass scan: 98 co-resident blocks.
__global__ void k_scan_one() {
    int b = blockIdx.x, t = threadIdx.x;
    int base = b * SCAN_CHUNK + t * 4;
    int d[4]; int s = 0;
#pragma unroll
    for (int i = 0; i < 4; ++i) {
        int idx = base + i;
        d[i] = (idx < N_NODES) ? g_deg[idx] : 0;
        s += d[i];
    }
    __shared__ int sm[256];
    sm[t] = s; __syncthreads();
    for (int off = 1; off < 256; off <<= 1) {
        int u = (t >= off) ? sm[t - off] : 0;
        __syncthreads();
        sm[t] += u;
        __syncthreads();
    }
    int chunk_total = sm[255];
    if (t == 0) {
        g_part[b] = chunk_total;
        __threadfence();
        atomicAdd(&g_flag, 1);
        while (atomicAdd(&g_flag, 0) < NPART) { }
    }
    __syncthreads();
    __threadfence();
    int v = (t < b) ? *((volatile int*)&g_part[t]) : 0;
    __shared__ int rs[256];
    rs[t] = v; __syncthreads();
    for (int off = 128; off > 0; off >>= 1) {
        if (t < off) rs[t] += rs[t + off];
        __syncthreads();
    }
    int prev = rs[0];
    int run = prev + sm[t] - s;
#pragma unroll
    for (int i = 0; i < 4; ++i) {
        int idx = base + i;
        if (idx < N_NODES) { g_off[idx] = run; g_cur[idx] = run; run += d[i]; }
    }
    if (b == NPART - 1 && t == 255) g_off[N_NODES] = prev + chunk_total;
}

// CSR fill: 4 edges/thread (vector loads for MLP).
__global__ void k_fill(const int* __restrict__ ei) {
    int t = blockIdx.x * blockDim.x + threadIdx.x;
    int e0 = t * 4;
    if (e0 >= N_EDGES) return;
    int s[4], d[4];
    if (g_stride == 2) {
        const long long* p = (const long long*)ei;
        longlong2 sa = *reinterpret_cast<const longlong2*>(&p[e0]);
        longlong2 sb = *reinterpret_cast<const longlong2*>(&p[e0 + 2]);
        longlong2 da = *reinterpret_cast<const longlong2*>(&p[N_EDGES + e0]);
        longlong2 db = *reinterpret_cast<const longlong2*>(&p[N_EDGES + e0 + 2]);
        s[0] = (int)sa.x; s[1] = (int)sa.y; s[2] = (int)sb.x; s[3] = (int)sb.y;
        d[0] = (int)da.x; d[1] = (int)da.y; d[2] = (int)db.x; d[3] = (int)db.y;
    } else {
        int4 sa = *reinterpret_cast<const int4*>(&ei[e0]);
        int4 da = *reinterpret_cast<const int4*>(&ei[N_EDGES + e0]);
        s[0] = sa.x; s[1] = sa.y; s[2] = sa.z; s[3] = sa.w;
        d[0] = da.x; d[1] = da.y; d[2] = da.z; d[3] = da.w;
    }
#pragma unroll
    for (int i = 0; i < 4; ++i) {
        if ((unsigned)s[i] < N_NODES && (unsigned)d[i] < N_NODES) {
            int pos = atomicAdd(&g_cur[d[i]], 1);
            g_adj[pos] = s[i];
        }
    }
}

// gather1a: nodes [0, NSPLIT_NODES), one warp per node.
__global__ void k_gather1a() {
    int gid = blockIdx.x * blockDim.x + threadIdx.x;
    int n = gid >> 5;
    if (n >= NSPLIT_NODES) return;
    gather1_body(n, gid & 31);
}

// mega3: gemm2 tiles [0, NSPLIT_TILES)  ||  gather1b.
__global__ __launch_bounds__(256) void k_mega3(const float* __restrict__ Wl,
                                               const float* __restrict__ Wr,
                                               const float* __restrict__ b1) {
    if (blockIdx.x < NSPLIT_TILES) {
        gemm2_tile(blockIdx.x, Wl, Wr, b1);
    } else {
        int gid = (blockIdx.x - NSPLIT_TILES) * 256 + threadIdx.x;
        int n = NSPLIT_NODES + (gid >> 5);
        if (n >= N_NODES) return;
        gather1_body(n, gid & 31);
    }
}

// gemm2b: remaining tiles.
__global__ __launch_bounds__(256) void k_gemm2b(const float* __restrict__ Wl,
                                                const float* __restrict__ Wr,
                                                const float* __restrict__ b1) {
    gemm2_tile(NSPLIT_TILES + blockIdx.x, Wl, Wr, b1);
}

// Fused gather2 + finish + head: 16 threads per node.
__global__ void k_g2final(const float* __restrict__ b2,
                          const float* __restrict__ Wh,
                          const float* __restrict__ bh,
                          float* __restrict__ out,
                          int write_emb, long long risk_off, int write_risk) {
    int gid = blockIdx.x * blockDim.x + threadIdx.x;
    int n = gid >> 4;
    int sub = gid & 15;
    if (n >= N_NODES) return;
    const __half2* __restrict__ hl2 = reinterpret_cast<const __half2*>(g_hlh);
    int i = g_off[n], end = g_off[n + 1];
    float sx = 0.f, sy = 0.f;
    for (; i + 1 < end; i += 2) {
        int s0 = g_adj[i], s1 = g_adj[i + 1];
        float2 a = __half22float2(hl2[(size_t)s0 * 16 + sub]);
        float2 b = __half22float2(hl2[(size_t)s1 * 16 + sub]);
        sx += a.x + b.x; sy += a.y + b.y;
    }
    if (i < end) {
        float2 a = __half22float2(hl2[(size_t)g_adj[i] * 16 + sub]);
        sx += a.x; sy += a.y;
    }
    float inv = 1.0f / (float)max(g_deg[n], 1);
    size_t o = (size_t)n * EMB + 2 * sub;
    float2 hr2 = *reinterpret_cast<const float2*>(&g_hr[o]);
    float2 bb = *reinterpret_cast<const float2*>(&b2[2 * sub]);
    float ex = fmaxf(fmaf(sx, inv, bb.x) + hr2.x, 0.f);
    float ey = fmaxf(fmaf(sy, inv, bb.y) + hr2.y, 0.f);
    if (write_emb)
        *reinterpret_cast<float2*>(&out[o]) = make_float2(ex, ey);
    float2 wh = *reinterpret_cast<const float2*>(&Wh[2 * sub]);
    float p = ex * wh.x + ey * wh.y;
#pragma unroll
    for (int off = 8; off > 0; off >>= 1)
        p += __shfl_xor_sync(0xFFFFFFFFu, p, off);
    if (write_risk && sub == 0)
        out[risk_off + n] = p + __ldg(&bh[0]);
}

// ---------------- launch ----------------
extern "C" void kernel_launch(void* const* d_in, const int* in_sizes, int n_in,
                              void* d_out, int out_size) {
    const float *x = 0, *W1_l = 0, *b1 = 0, *W1_r = 0, *W2_l = 0, *b2 = 0,
                *W2_r = 0, *Wh = 0, *bh = 0;
    const int* ei = 0;
    int n8192 = 0, n2048 = 0, n32 = 0;
    for (int i = 0; i < n_in; ++i) {
        int sz = in_sizes[i];
        const void* p = d_in[i];
        if (sz == N_NODES * IN_F)                        x = (const float*)p;
        else if (sz == 2 * N_EDGES || sz == 4 * N_EDGES) ei = (const int*)p;
        else if (sz == IN_F * HID) { if (n8192++ == 0) W1_l = (const float*)p; else W1_r = (const float*)p; }
        else if (sz == HID * EMB)  { if (n2048++ == 0) W2_l = (const float*)p; else W2_r = (const float*)p; }
        else if (sz == HID)        b1 = (const float*)p;
        else if (sz == EMB)        { if (n32++ == 0) b2 = (const float*)p; else Wh = (const float*)p; }
        else if (sz == 1)          bh = (const float*)p;
    }
    float* out = (float*)d_out;

    int write_emb = (out_size >= N_NODES * EMB) ? 1 : 0;
    long long risk_off = write_emb ? (long long)N_NODES * EMB : 0;
    int write_risk = (out_size - (write_emb ? N_NODES * EMB : 0) >= N_NODES) ? 1 : 0;

    cudaStream_t sb;
    cudaStreamCreateWithFlags(&sb, cudaStreamNonBlocking);
    cudaEvent_t eA, eB;
    cudaEventCreateWithFlags(&eA, cudaEventDisableTiming);
    cudaEventCreateWithFlags(&eB, cudaEventDisableTiming);

    // S0: init
    k_init<<<(N_NODES + 255) / 256, 256>>>(ei);
    cudaEventRecord(eA, 0);

    // SB: edge chain (vectorized 4 edges/thread)
    cudaStreamWaitEvent(sb, eA, 0);
    k_degree<<<EB4, 256, 0, sb>>>(ei);
    k_scan_one<<<NPART, 256, 0, sb>>>();
    k_fill<<<EB4, 256, 0, sb>>>(ei);
    cudaEventRecord(eB, sb);

    // S0: WMMA layer-1 GEMM, concurrent with edge chain
    k_gemm1<<<GEMM_BLOCKS, 256>>>(x, W1_l, W1_r);

    // join
    cudaStreamWaitEvent(0, eB, 0);
    k_gather1a<<<G1A_BLOCKS, 256>>>();
    k_mega3<<<NSPLIT_TILES + G1B_BLOCKS, 256>>>(W2_l, W2_r, b1);
    k_gemm2b<<<GEMM2B_BLOCKS, 256>>>(W2_l, W2_r, b1);
    {
        int threads = 256;
        int blocks = (N_NODES * 16 + threads - 1) / threads;  // 6250
        k_g2final<<<blocks, threads>>>(b2, Wh, bh, out, write_emb, risk_off, write_risk);
    }
}

// round 16
// speedup vs baseline: 1.0539x; 1.0539x over previous
#include <cuda_runtime.h>
#include <cuda_fp16.h>
#include <cstdint>

#define N_NODES 100000
#define N_EDGES 1600000
#define IN_F 128
#define HID 64
#define EMB 32
#define SCAN_CHUNK 1024
#define NPART ((N_NODES + SCAN_CHUNK - 1) / SCAN_CHUNK)   // 98

#define GEMM_BLOCKS ((N_NODES + 63) / 64)                 // 1563
#define EB  ((N_EDGES + 255) / 256)                       // 6250

#define NSPLIT_TILES 782
#define NSPLIT_NODES (NSPLIT_TILES * 64)                  // 50048
#define G1A_BLOCKS (NSPLIT_NODES * 32 / 256)              // 6256
#define G1B_BLOCKS ((N_NODES - NSPLIT_NODES) * 32 / 256 + 1)
#define GEMM2B_BLOCKS (GEMM_BLOCKS - NSPLIT_TILES)        // 781

// ---------------- scratch (device globals; referenced ONLY in device code) ----
__device__ __align__(16) __half g_xlh[N_NODES * HID];    // x @ W1_l   (fp16)
__device__ __align__(16) float  g_xr [N_NODES * HID];    // x @ W1_r   (fp32)
__device__ __align__(16) float  g_agg1[N_NODES * HID];   // segment_sum of xl
__device__ __align__(16) __half g_hlh[N_NODES * EMB];    // h @ W2_l   (fp16)
__device__ __align__(16) float  g_hr [N_NODES * EMB];    // h @ W2_r   (fp32)
__device__ int g_deg[N_NODES];
__device__ int g_off[N_NODES + 1];
__device__ int g_adj[N_EDGES];
__device__ int g_rank[N_EDGES];                           // edge rank within dst list
__device__ int g_part[NPART];
__device__ int g_flag;                                    // scan arrival counter
__device__ int g_stride;                                  // 1 = int32, 2 = int64

// ---------------- device bodies ----------------

// One 64-row M-tile of the layer-1 dual GEMM (packed fma.rn.f32x2).
__device__ __forceinline__ void gemm1_tile(int tile,
                                           const float* __restrict__ X,
                                           const float* __restrict__ Wl,
                                           const float* __restrict__ Wr) {
    __shared__ __align__(16) float ws[32][128];
    __shared__ __align__(16) float xs[32][64];   // transposed: xs[k][m]

    int tid = threadIdx.x;
    int n0 = tile * 64;
    int rows = N_NODES - n0; if (rows > 64) rows = 64;
    int ty = tid >> 4, tx = tid & 15;
    int m0 = ty * 4;

    unsigned long long acc[4][4];
#pragma unroll
    for (int i = 0; i < 4; ++i)
#pragma unroll
        for (int j = 0; j < 4; ++j) acc[i][j] = 0ull;

    for (int kc = 0; kc < IN_F; kc += 32) {
        for (int idx = tid; idx < 1024; idx += 256) {   // 32*128/4
            int k = idx >> 5;
            int n = (idx & 31) * 4;
            const float* src = (n < 64) ? &Wl[(kc + k) * 64 + n]
                                        : &Wr[(kc + k) * 64 + (n - 64)];
            *reinterpret_cast<float4*>(&ws[k][n]) =
                *reinterpret_cast<const float4*>(src);
        }
        for (int idx = tid; idx < 512; idx += 256) {    // 64*32/4
            int m = idx & 63;
            int kv = (idx >> 6) * 4;
            int gr = n0 + m; if (gr >= N_NODES) gr = N_NODES - 1;
            float4 v = *reinterpret_cast<const float4*>(&X[(size_t)gr * IN_F + kc + kv]);
            xs[kv + 0][m] = v.x; xs[kv + 1][m] = v.y;
            xs[kv + 2][m] = v.z; xs[kv + 3][m] = v.w;
        }
        __syncthreads();

#pragma unroll
        for (int k = 0; k < 32; ++k) {
            unsigned long long xv[4];
#pragma unroll
            for (int i = 0; i < 4; ++i) {
                float xf = xs[k][m0 + i];
                asm("mov.b64 %0, {%1, %1};" : "=l"(xv[i]) : "f"(xf));
            }
            unsigned long long wv[4];
#pragma unroll
            for (int j = 0; j < 4; ++j)
                wv[j] = *reinterpret_cast<const unsigned long long*>(&ws[k][2 * tx + 32 * j]);
#pragma unroll
            for (int i = 0; i < 4; ++i)
#pragma unroll
                for (int j = 0; j < 4; ++j)
                    asm("fma.rn.f32x2 %0, %1, %2, %0;"
                        : "+l"(acc[i][j]) : "l"(xv[i]), "l"(wv[j]));
        }
        __syncthreads();
    }

#pragma unroll
    for (int j = 0; j < 4; ++j) {
        int n = 2 * tx + 32 * j;
#pragma unroll
        for (int i = 0; i < 4; ++i) {
            if (m0 + i < rows) {
                float lo, hi;
                asm("mov.b64 {%0, %1}, %2;" : "=f"(lo), "=f"(hi) : "l"(acc[i][j]));
                size_t row = (size_t)(n0 + m0 + i);
                if (n < 64) {
                    *reinterpret_cast<__half2*>(&g_xlh[row * HID + n]) =
                        __floats2half2_rn(lo, hi);
                } else {
                    *reinterpret_cast<float2*>(&g_xr[row * HID + (n - 64)]) =
                        make_float2(lo, hi);
                }
            }
        }
    }
}

// One 64-row M-tile of the layer-2 dual GEMM with fused layer-1 finish.
__device__ __forceinline__ void gemm2_tile(int tile,
                                           const float* __restrict__ Wl,
                                           const float* __restrict__ Wr,
                                           const float* __restrict__ b1) {
    __shared__ __align__(16) float ws2[32][64];
    __shared__ __align__(16) float xs2[32][64];

    int tid = threadIdx.x;
    int n0 = tile * 64;
    int rows = N_NODES - n0; if (rows > 64) rows = 64;
    int ty = tid >> 4, tx = tid & 15;
    int m0 = ty * 4;

    unsigned long long acc[4][2];
#pragma unroll
    for (int i = 0; i < 4; ++i)
#pragma unroll
        for (int j = 0; j < 2; ++j) acc[i][j] = 0ull;

    for (int kc = 0; kc < HID; kc += 32) {
        for (int idx = tid; idx < 512; idx += 256) {
            int k = idx >> 4;
            int n = (idx & 15) * 4;
            const float* src = (n < 32) ? &Wl[(kc + k) * 32 + n]
                                        : &Wr[(kc + k) * 32 + (n - 32)];
            *reinterpret_cast<float4*>(&ws2[k][n]) =
                *reinterpret_cast<const float4*>(src);
        }
        for (int idx = tid; idx < 512; idx += 256) {
            int m = idx & 63;
            int kv = (idx >> 6) * 4;
            int gr = n0 + m; if (gr >= N_NODES) gr = N_NODES - 1;
            float inv = 1.0f / (float)max(g_deg[gr], 1);
            float4 a = *reinterpret_cast<const float4*>(&g_agg1[(size_t)gr * HID + kc + kv]);
            float4 r = *reinterpret_cast<const float4*>(&g_xr[(size_t)gr * HID + kc + kv]);
            float4 b = *reinterpret_cast<const float4*>(&b1[kc + kv]);
            xs2[kv + 0][m] = fmaxf(fmaf(a.x, inv, b.x) + r.x, 0.f);
            xs2[kv + 1][m] = fmaxf(fmaf(a.y, inv, b.y) + r.y, 0.f);
            xs2[kv + 2][m] = fmaxf(fmaf(a.z, inv, b.z) + r.z, 0.f);
            xs2[kv + 3][m] = fmaxf(fmaf(a.w, inv, b.w) + r.w, 0.f);
        }
        __syncthreads();

#pragma unroll
        for (int k = 0; k < 32; ++k) {
            unsigned long long xv[4];
#pragma unroll
            for (int i = 0; i < 4; ++i) {
                float xf = xs2[k][m0 + i];
                asm("mov.b64 %0, {%1, %1};" : "=l"(xv[i]) : "f"(xf));
            }
            unsigned long long wv[2];
#pragma unroll
            for (int j = 0; j < 2; ++j)
                wv[j] = *reinterpret_cast<const unsigned long long*>(&ws2[k][2 * tx + 32 * j]);
#pragma unroll
            for (int i = 0; i < 4; ++i)
#pragma unroll
                for (int j = 0; j < 2; ++j)
                    asm("fma.rn.f32x2 %0, %1, %2, %0;"
                        : "+l"(acc[i][j]) : "l"(xv[i]), "l"(wv[j]));
        }
        __syncthreads();
    }

#pragma unroll
    for (int j = 0; j < 2; ++j) {
        int n = 2 * tx + 32 * j;
#pragma unroll
        for (int i = 0; i < 4; ++i) {
            if (m0 + i < rows) {
                float lo, hi;
                asm("mov.b64 {%0, %1}, %2;" : "=f"(lo), "=f"(hi) : "l"(acc[i][j]));
                size_t row = (size_t)(n0 + m0 + i);
                if (n < 32) {
                    *reinterpret_cast<__half2*>(&g_hlh[row * EMB + n]) =
                        __floats2half2_rn(lo, hi);
                } else {
                    *reinterpret_cast<float2*>(&g_hr[row * EMB + (n - 32)]) =
                        make_float2(lo, hi);
                }
            }
        }
    }
}

// Gather body for one (node, lane) pair: lane sums half2 column pair.
__device__ __forceinline__ void gather1_body(int n, int lane) {
    const __half2* __restrict__ xl2 = reinterpret_cast<const __half2*>(g_xlh);
    int i = g_off[n], end = g_off[n + 1];
    float sx = 0.f, sy = 0.f;
    for (; i + 1 < end; i += 2) {
        int s0 = g_adj[i], s1 = g_adj[i + 1];
        float2 a = __half22float2(xl2[(size_t)s0 * 32 + lane]);
        float2 b = __half22float2(xl2[(size_t)s1 * 32 + lane]);
        sx += a.x + b.x; sy += a.y + b.y;
    }
    if (i < end) {
        float2 a = __half22float2(xl2[(size_t)g_adj[i] * 32 + lane]);
        sx += a.x; sy += a.y;
    }
    *reinterpret_cast<float2*>(&g_agg1[(size_t)n * HID + 2 * lane]) =
        make_float2(sx, sy);
}

// ---------------- kernels ----------------

// init: zero g_deg + scan flag; block 0 detects index dtype.
__global__ void k_init(const int* __restrict__ w) {
    int i = blockIdx.x * blockDim.x + threadIdx.x;
    if (i < N_NODES) g_deg[i] = 0;
    if (i == 0) g_flag = 0;
    if (blockIdx.x == 0) {
        __shared__ int nz;
        if (threadIdx.x == 0) nz = 0;
        __syncthreads();
        int cnt = 0;
        for (int k = threadIdx.x; k < 4096; k += blockDim.x)
            if (w[2 * k + 1] != 0) cnt++;
        atomicAdd(&nz, cnt);
        __syncthreads();
        if (threadIdx.x == 0) g_stride = (nz == 0) ? 2 : 1;
    }
}

// Full layer-1 GEMM (f32x2; standalone).
__global__ __launch_bounds__(256) void k_gemm1(const float* __restrict__ X,
                                               const float* __restrict__ Wl,
                                               const float* __restrict__ Wr) {
    gemm1_tile(blockIdx.x, X, Wl, Wr);
}

// Degree histogram + per-edge rank capture: the atomic's return value IS the
// edge's rank within its destination list — stored for the atomic-free fill.
__global__ void k_degree(const int* __restrict__ ei) {
    int e = blockIdx.x * blockDim.x + threadIdx.x;
    if (e >= N_EDGES) return;
    int st = g_stride;
    int d = ei[((size_t)N_EDGES + e) * st];
    if ((unsigned)d < N_NODES)
        g_rank[e] = atomicAdd(&g_deg[d], 1);
}

// Single-pass scan: 98 co-resident blocks (no g_cur needed anymore).
__global__ void k_scan_one() {
    int b = blockIdx.x, t = threadIdx.x;
    int base = b * SCAN_CHUNK + t * 4;
    int d[4]; int s = 0;
#pragma unroll
    for (int i = 0; i < 4; ++i) {
        int idx = base + i;
        d[i] = (idx < N_NODES) ? g_deg[idx] : 0;
        s += d[i];
    }
    __shared__ int sm[256];
    sm[t] = s; __syncthreads();
    for (int off = 1; off < 256; off <<= 1) {
        int u = (t >= off) ? sm[t - off] : 0;
        __syncthreads();
        sm[t] += u;
        __syncthreads();
    }
    int chunk_total = sm[255];
    if (t == 0) {
        g_part[b] = chunk_total;
        __threadfence();
        atomicAdd(&g_flag, 1);
        while (atomicAdd(&g_flag, 0) < NPART) { }
    }
    __syncthreads();
    __threadfence();
    int v = (t < b) ? *((volatile int*)&g_part[t]) : 0;
    __shared__ int rs[256];
    rs[t] = v; __syncthreads();
    for (int off = 128; off > 0; off >>= 1) {
        if (t < off) rs[t] += rs[t + off];
        __syncthreads();
    }
    int prev = rs[0];
    int run = prev + sm[t] - s;
#pragma unroll
    for (int i = 0; i < 4; ++i) {
        int idx = base + i;
        if (idx < N_NODES) { g_off[idx] = run; run += d[i]; }
    }
    if (b == NPART - 1 && t == 255) g_off[N_NODES] = prev + chunk_total;
}

// CSR fill, ATOMIC-FREE: adj[off[d] + rank[e]] = s.
__global__ void k_fill(const int* __restrict__ ei) {
    int e = blockIdx.x * blockDim.x + threadIdx.x;
    if (e >= N_EDGES) return;
    int st = g_stride;
    int s = ei[(size_t)e * st];
    int d = ei[((size_t)N_EDGES + e) * st];
    if ((unsigned)s >= N_NODES || (unsigned)d >= N_NODES) return;
    g_adj[g_off[d] + g_rank[e]] = s;
}

// gather1a: nodes [0, NSPLIT_NODES), one warp per node.
__global__ void k_gather1a() {
    int gid = blockIdx.x * blockDim.x + threadIdx.x;
    int n = gid >> 5;
    if (n >= NSPLIT_NODES) return;
    gather1_body(n, gid & 31);
}

// mega3: gemm2 tiles [0, NSPLIT_TILES)  ||  gather1b (nodes >= NSPLIT_NODES).
__global__ __launch_bounds__(256) void k_mega3(const float* __restrict__ Wl,
                                               const float* __restrict__ Wr,
                                               const float* __restrict__ b1) {
    if (blockIdx.x < NSPLIT_TILES) {
        gemm2_tile(blockIdx.x, Wl, Wr, b1);
    } else {
        int gid = (blockIdx.x - NSPLIT_TILES) * 256 + threadIdx.x;
        int n = NSPLIT_NODES + (gid >> 5);
        if (n >= N_NODES) return;
        gather1_body(n, gid & 31);
    }
}

// gemm2b: remaining tiles.
__global__ __launch_bounds__(256) void k_gemm2b(const float* __restrict__ Wl,
                                                const float* __restrict__ Wr,
                                                const float* __restrict__ b1) {
    gemm2_tile(NSPLIT_TILES + blockIdx.x, Wl, Wr, b1);
}

// Fused gather2 + finish + head: 16 threads per node.
__global__ void k_g2final(const float* __restrict__ b2,
                          const float* __restrict__ Wh,
                          const float* __restrict__ bh,
                          float* __restrict__ out,
                          int write_emb, long long risk_off, int write_risk) {
    int gid = blockIdx.x * blockDim.x + threadIdx.x;
    int n = gid >> 4;
    int sub = gid & 15;
    if (n >= N_NODES) return;
    const __half2* __restrict__ hl2 = reinterpret_cast<const __half2*>(g_hlh);
    int i = g_off[n], end = g_off[n + 1];
    float sx = 0.f, sy = 0.f;
    for (; i + 1 < end; i += 2) {
        int s0 = g_adj[i], s1 = g_adj[i + 1];
        float2 a = __half22float2(hl2[(size_t)s0 * 16 + sub]);
        float2 b = __half22float2(hl2[(size_t)s1 * 16 + sub]);
        sx += a.x + b.x; sy += a.y + b.y;
    }
    if (i < end) {
        float2 a = __half22float2(hl2[(size_t)g_adj[i] * 16 + sub]);
        sx += a.x; sy += a.y;
    }
    float inv = 1.0f / (float)max(g_deg[n], 1);
    size_t o = (size_t)n * EMB + 2 * sub;
    float2 hr2 = *reinterpret_cast<const float2*>(&g_hr[o]);
    float2 bb = *reinterpret_cast<const float2*>(&b2[2 * sub]);
    float ex = fmaxf(fmaf(sx, inv, bb.x) + hr2.x, 0.f);
    float ey = fmaxf(fmaf(sy, inv, bb.y) + hr2.y, 0.f);
    if (write_emb)
        *reinterpret_cast<float2*>(&out[o]) = make_float2(ex, ey);
    float2 wh = *reinterpret_cast<const float2*>(&Wh[2 * sub]);
    float p = ex * wh.x + ey * wh.y;
#pragma unroll
    for (int off = 8; off > 0; off >>= 1)
        p += __shfl_xor_sync(0xFFFFFFFFu, p, off);
    if (write_risk && sub == 0)
        out[risk_off + n] = p + __ldg(&bh[0]);
}

// ---------------- launch ----------------
extern "C" void kernel_launch(void* const* d_in, const int* in_sizes, int n_in,
                              void* d_out, int out_size) {
    const float *x = 0, *W1_l = 0, *b1 = 0, *W1_r = 0, *W2_l = 0, *b2 = 0,
                *W2_r = 0, *Wh = 0, *bh = 0;
    const int* ei = 0;
    int n8192 = 0, n2048 = 0, n32 = 0;
    for (int i = 0; i < n_in; ++i) {
        int sz = in_sizes[i];
        const void* p = d_in[i];
        if (sz == N_NODES * IN_F)                        x = (const float*)p;
        else if (sz == 2 * N_EDGES || sz == 4 * N_EDGES) ei = (const int*)p;
        else if (sz == IN_F * HID) { if (n8192++ == 0) W1_l = (const float*)p; else W1_r = (const float*)p; }
        else if (sz == HID * EMB)  { if (n2048++ == 0) W2_l = (const float*)p; else W2_r = (const float*)p; }
        else if (sz == HID)        b1 = (const float*)p;
        else if (sz == EMB)        { if (n32++ == 0) b2 = (const float*)p; else Wh = (const float*)p; }
        else if (sz == 1)          bh = (const float*)p;
    }
    float* out = (float*)d_out;

    int write_emb = (out_size >= N_NODES * EMB) ? 1 : 0;
    long long risk_off = write_emb ? (long long)N_NODES * EMB : 0;
    int write_risk = (out_size - (write_emb ? N_NODES * EMB : 0) >= N_NODES) ? 1 : 0;

    // Capture-forked side stream (documented graph-capture fork/join pattern).
    cudaStream_t sb;
    cudaStreamCreateWithFlags(&sb, cudaStreamNonBlocking);
    cudaEvent_t eA, eB;
    cudaEventCreateWithFlags(&eA, cudaEventDisableTiming);
    cudaEventCreateWithFlags(&eB, cudaEventDisableTiming);

    // S0: init
    k_init<<<(N_NODES + 255) / 256, 256>>>(ei);
    cudaEventRecord(eA, 0);

    // SB: edge chain (degree+rank -> scan -> atomic-free fill)
    cudaStreamWaitEvent(sb, eA, 0);
    k_degree<<<EB, 256, 0, sb>>>(ei);
    k_scan_one<<<NPART, 256, 0, sb>>>();
    k_fill<<<EB, 256, 0, sb>>>(ei);
    cudaEventRecord(eB, sb);

    // S0: layer-1 GEMM, concurrent with edge chain
    k_gemm1<<<GEMM_BLOCKS, 256>>>(x, W1_l, W1_r);

    // join
    cudaStreamWaitEvent(0, eB, 0);
    k_gather1a<<<G1A_BLOCKS, 256>>>();
    k_mega3<<<NSPLIT_TILES + G1B_BLOCKS, 256>>>(W2_l, W2_r, b1);
    k_gemm2b<<<GEMM2B_BLOCKS, 256>>>(W2_l, W2_r, b1);
    {
        int threads = 256;
        int blocks = (N_NODES * 16 + threads - 1) / threads;  // 6250
        k_g2final<<<blocks, threads>>>(b2, Wh, bh, out, write_emb, risk_off, write_risk);
    }
}